// round 6
// baseline (speedup 1.0000x reference)
#include <cuda_runtime.h>
#include <cuda_fp16.h>
#include <math.h>
#include <stdint.h>

#define SS 512
#define BB 256
#define DD 256
#define NROWS (SS*BB)          // 131072
#define JROWS ((SS-2)*BB)      // 130560

// ---------------- scratch ----------------
__device__ __align__(256) __half g_src[(size_t)NROWS*DD];
__device__ __align__(256) __half g_h[(size_t)NROWS*DD];
__device__ __align__(256) __half g_t[(size_t)NROWS*DD];
__device__ __align__(256) __half g_mw[DD*DD];
__device__ __align__(256) __half g_w[DD*2*DD];

// ---------------- helpers ----------------
__device__ __forceinline__ uint32_t smem_u32(const void* p) {
    uint32_t r;
    asm("{ .reg .u64 t; cvta.to.shared.u64 t, %1; cvt.u32.u64 %0, t; }" : "=r"(r) : "l"(p));
    return r;
}
__device__ __forceinline__ void cp16z(uint32_t dst, const void* src, uint32_t sz) {
    asm volatile("cp.async.cg.shared.global [%0], [%1], 16, %2;" :: "r"(dst), "l"(src), "r"(sz));
}
__device__ __forceinline__ void cp16(uint32_t dst, const void* src) {
    asm volatile("cp.async.cg.shared.global [%0], [%1], 16;" :: "r"(dst), "l"(src));
}
__device__ __forceinline__ void ldmx4(uint32_t* r, uint32_t addr) {
    asm volatile("ldmatrix.sync.aligned.m8n8.x4.shared.b16 {%0,%1,%2,%3}, [%4];"
                 : "=r"(r[0]), "=r"(r[1]), "=r"(r[2]), "=r"(r[3]) : "r"(addr));
}
__device__ __forceinline__ void mma16816(float* d, const uint32_t* a, uint32_t b0, uint32_t b1) {
    asm volatile("mma.sync.aligned.m16n8k16.row.col.f32.f16.f16.f32 "
                 "{%0,%1,%2,%3}, {%4,%5,%6,%7}, {%8,%9}, {%0,%1,%2,%3};"
                 : "+f"(d[0]), "+f"(d[1]), "+f"(d[2]), "+f"(d[3])
                 : "r"(a[0]), "r"(a[1]), "r"(a[2]), "r"(a[3]), "r"(b0), "r"(b1));
}
__device__ __forceinline__ float gelu_f(float x) {
    return 0.5f * x * (1.0f + erff(x * 0.7071067811865476f));
}
// swizzled offset within an Nrows x 64-col fp16 tile (128B rows, 8 x 16B chunks)
__device__ __forceinline__ uint32_t swz(int r, int c) {
    return (uint32_t)(r * 128 + ((c ^ (r & 7)) * 16));
}

// ---------------- fp32 -> fp16 ----------------
__global__ void conv_k(const float* __restrict__ in, __half* __restrict__ o, int n) {
    int i = (blockIdx.x * blockDim.x + threadIdx.x) * 4;
    if (i >= n) return;
    float4 v = *(const float4*)(in + i);
    __half2 t;
    t.x = __float2half(v.x); t.y = __float2half(v.y); *(__half2*)(o + i)     = t;
    t.x = __float2half(v.z); t.y = __float2half(v.w); *(__half2*)(o + i + 2) = t;
}

// ---------------- mma.sync GEMM, single fp16, full-N CTA tile ----------------
// CTA tile 128(M) x 256(N); 512 threads = 16 warps as 4(M) x 4(N); warp tile 32x64.
// K-chunk 64, 3-stage cp.async pipeline.
// out = gelu( A1[n+a1_off] @ W[:, :256]^T (+ A2 @ W[:, 256:]^T) + bias )
// MODE 0: outh = fp16(gelu(.))
// MODE 1: outf = x + gelu(.), x = a1[row+a1_off] (0 if row<0)
// MODE 2: outf[row+out_off] += gelu(.)
#define NSTG 3
#define STGB 49152            // A 16K + W 32K per stage
#define SMEM_BYTES (1024 + NSTG*STGB)

template<int KTOT, int MODE>
__global__ void __launch_bounds__(512, 1) mma_gemm(
    const __half* __restrict__ a1, int a1_off,
    const __half* __restrict__ a2, int a2_off,
    const __half* __restrict__ w,
    const float* __restrict__ bias,
    float* __restrict__ outf, int out_off,
    __half* __restrict__ outh)
{
    constexpr int NCH = KTOT / 64;
    extern __shared__ char smraw[];
    const uint32_t TIL = (smem_u32(smraw) + 1023u) & ~1023u;

    const int tid  = threadIdx.x;
    const int wid  = tid >> 5;
    const int lane = tid & 31;
    const int wm   = wid & 3;          // M warp (0..3) -> rows wm*32..+32
    const int wn   = wid >> 2;         // N warp (0..3) -> cols wn*64..+64
    const int mbase = blockIdx.x * 128;

    float acc[2][8][4];
    #pragma unroll
    for (int i = 0; i < 2; i++)
        #pragma unroll
        for (int j = 0; j < 8; j++)
            #pragma unroll
            for (int k = 0; k < 4; k++) acc[i][j][k] = 0.f;

    auto load_chunk = [&](int c, int stg) {
        const int k = c * 64;
        const __half* A_;
        int aoff, kk;
        if (KTOT == 512 && k >= 256) { A_ = a2; aoff = a2_off; kk = k - 256; }
        else                         { A_ = a1; aoff = a1_off; kk = k; }
        const uint32_t sb = TIL + (uint32_t)stg * STGB;
        #pragma unroll
        for (int v = tid; v < 3072; v += 512) {
            if (v < 1024) {                      // A: 128 rows x 8 x 16B
                int r = v >> 3, cc = v & 7;
                int grow = mbase + r + aoff;
                uint32_t sz = 16; int g = grow;
                if (g < 0) { g = 0; sz = 0; }
                cp16z(sb + swz(r, cc), A_ + (size_t)g * DD + kk + cc * 8, sz);
            } else {                             // W: 256 rows x 8 x 16B
                int v2 = v - 1024;
                int r = v2 >> 3, cc = v2 & 7;
                cp16(sb + 16384u + swz(r, cc), w + (size_t)r * KTOT + k + cc * 8);
            }
        }
        asm volatile("cp.async.commit_group;" ::: "memory");
    };

    load_chunk(0, 0);
    if (NCH > 1) load_chunk(1, 1);

    for (int c = 0; c < NCH; ++c) {
        if (c == NCH - 1) asm volatile("cp.async.wait_group 0;" ::: "memory");
        else              asm volatile("cp.async.wait_group 1;" ::: "memory");
        __syncthreads();
        if (c + 2 < NCH) load_chunk(c + 2, (c + 2) % NSTG);

        const uint32_t sA = TIL + (uint32_t)(c % NSTG) * STGB;
        const uint32_t sW = sA + 16384;
        #pragma unroll
        for (int kh = 0; kh < 4; kh++) {
            const int c0 = kh * 2;               // 16B-chunk base within 128B row
            uint32_t a[2][4];
            #pragma unroll
            for (int mf = 0; mf < 2; mf++) {
                int r  = wm * 32 + mf * 16 + (lane & 15);
                int cc = c0 + (lane >> 4);
                ldmx4(a[mf], sA + swz(r, cc));
            }
            uint32_t b[8][2];
            #pragma unroll
            for (int nb = 0; nb < 4; nb++) {
                int r  = wn * 64 + nb * 16 + (lane & 7) + ((lane >> 4) << 3);
                int cc = c0 + ((lane >> 3) & 1);
                uint32_t t4[4];
                ldmx4(t4, sW + swz(r, cc));
                b[2 * nb][0] = t4[0];     b[2 * nb][1] = t4[1];
                b[2 * nb + 1][0] = t4[2]; b[2 * nb + 1][1] = t4[3];
            }
            #pragma unroll
            for (int mf = 0; mf < 2; mf++)
                #pragma unroll
                for (int nf = 0; nf < 8; nf++)
                    mma16816(acc[mf][nf], a[mf], b[nf][0], b[nf][1]);
        }
    }

    // ---------------- epilogue ----------------
    float2 bn[8];
    #pragma unroll
    for (int nf = 0; nf < 8; nf++) {
        int col = wn * 64 + nf * 8 + (lane & 3) * 2;
        bn[nf].x = bias[col];
        bn[nf].y = bias[col + 1];
    }

    #pragma unroll
    for (int mf = 0; mf < 2; mf++) {
        #pragma unroll
        for (int half = 0; half < 2; half++) {
            const int row = mbase + wm * 32 + mf * 16 + (lane >> 2) + half * 8;
            const int colb = wn * 64 + (lane & 3) * 2;
            #pragma unroll
            for (int nf = 0; nf < 8; nf++) {
                const int col = colb + nf * 8;
                float g0 = gelu_f(acc[mf][nf][half * 2 + 0] + bn[nf].x);
                float g1 = gelu_f(acc[mf][nf][half * 2 + 1] + bn[nf].y);
                if (MODE == 0) {
                    const size_t ob = (size_t)row * DD + col;
                    __half2 hv;
                    hv.x = __float2half(g0);
                    hv.y = __float2half(g1);
                    *reinterpret_cast<__half2*>(outh + ob) = hv;
                } else if (MODE == 1) {
                    const size_t ob = (size_t)row * DD + col;
                    const int xr = row + a1_off;
                    float2 o;
                    if (xr >= 0) {
                        const size_t xb = (size_t)xr * DD + col;
                        __half2 xh2 = *reinterpret_cast<const __half2*>(a1 + xb);
                        o.x = g0 + __half2float(xh2.x);
                        o.y = g1 + __half2float(xh2.y);
                    } else { o.x = g0; o.y = g1; }
                    *reinterpret_cast<float2*>(outf + ob) = o;
                } else {
                    const size_t ob = (size_t)(row + out_off) * DD + col;
                    float2 o = *reinterpret_cast<float2*>(outf + ob);
                    o.x += g0; o.y += g1;
                    *reinterpret_cast<float2*>(outf + ob) = o;
                }
            }
        }
    }
}

// ---------------- cumsum over axis 0, in place ----------------
__global__ void cumsum_k(float* __restrict__ out) {
    int c = blockIdx.x * blockDim.x + threadIdx.x;
    float run = 0.f;
    #pragma unroll 8
    for (int s = 0; s < SS; s++) {
        size_t idx = (size_t)s * (BB * DD) + c;
        run += out[idx];
        out[idx] = run;
    }
}

extern "C" void kernel_launch(void* const* d_in, const int* in_sizes, int n_in,
                              void* d_out, int out_size)
{
    const float* src = nullptr; const float* map_w = nullptr; const float* bl_w = nullptr;
    const float* map_b = nullptr; const float* bl_b = nullptr;
    for (int i = 0; i < n_in; i++) {
        if (in_sizes[i] == NROWS * DD)       src   = (const float*)d_in[i];
        else if (in_sizes[i] == DD * DD)     map_w = (const float*)d_in[i];
        else if (in_sizes[i] == DD * 2 * DD) bl_w  = (const float*)d_in[i];
        else if (in_sizes[i] == DD) { if (!map_b) map_b = (const float*)d_in[i]; else bl_b = (const float*)d_in[i]; }
    }
    float* out = (float*)d_out;

    __half *sf, *h, *t, *mw, *w;
    cudaGetSymbolAddress((void**)&sf, g_src);
    cudaGetSymbolAddress((void**)&h,  g_h);
    cudaGetSymbolAddress((void**)&t,  g_t);
    cudaGetSymbolAddress((void**)&mw, g_mw);
    cudaGetSymbolAddress((void**)&w,  g_w);

    cudaFuncSetAttribute(mma_gemm<256, 0>, cudaFuncAttributeMaxDynamicSharedMemorySize, SMEM_BYTES);
    cudaFuncSetAttribute(mma_gemm<512, 0>, cudaFuncAttributeMaxDynamicSharedMemorySize, SMEM_BYTES);
    cudaFuncSetAttribute(mma_gemm<512, 1>, cudaFuncAttributeMaxDynamicSharedMemorySize, SMEM_BYTES);
    cudaFuncSetAttribute(mma_gemm<512, 2>, cudaFuncAttributeMaxDynamicSharedMemorySize, SMEM_BYTES);

    conv_k<<<(NROWS * DD / 4 + 255) / 256, 256>>>(src, sf, NROWS * DD);
    conv_k<<<(DD * DD / 4 + 255) / 256, 256>>>(map_w, mw, DD * DD);
    conv_k<<<(DD * 2 * DD / 4 + 255) / 256, 256>>>(bl_w, w, DD * 2 * DD);

    dim3 blk(512);
    const int gAll = NROWS / 128;   // 1024
    const int gJ   = JROWS / 128;   // 1020

    // 1) h = gelu(src @ map_w^T + map_b) -> fp16
    mma_gemm<256, 0><<<gAll, blk, SMEM_BYTES>>>(sf, 0, sf, 0, mw, map_b,
                                                nullptr, 0, h);
    // 2) delta = x + blacket(x, h), x = h shifted by one step (BB rows)
    mma_gemm<512, 1><<<gAll, blk, SMEM_BYTES>>>(h, -BB, h, 0, w, bl_b,
                                                out, 0, nullptr);
    // 3) J terms: t = blacket(u, v); out[2B:] += blacket(w, t)
    mma_gemm<512, 0><<<gJ, blk, SMEM_BYTES>>>(h, BB,     h, 2 * BB, w, bl_b,
                                              nullptr, 0, t);
    mma_gemm<512, 2><<<gJ, blk, SMEM_BYTES>>>(h, 0,      t, 0,      w, bl_b,
                                              out, 2 * BB, nullptr);
    mma_gemm<512, 0><<<gJ, blk, SMEM_BYTES>>>(h, 2 * BB, h, 0,      w, bl_b,
                                              nullptr, 0, t);
    mma_gemm<512, 2><<<gJ, blk, SMEM_BYTES>>>(h, BB,     t, 0,      w, bl_b,
                                              out, 2 * BB, nullptr);
    mma_gemm<512, 0><<<gJ, blk, SMEM_BYTES>>>(h, 0,      h, BB,     w, bl_b,
                                              nullptr, 0, t);
    mma_gemm<512, 2><<<gJ, blk, SMEM_BYTES>>>(h, 2 * BB, t, 0,      w, bl_b,
                                              out, 2 * BB, nullptr);
    // 4) cumsum along axis 0
    cumsum_k<<<(BB * DD) / 256, 256>>>(out);
}

// round 7
// speedup vs baseline: 1.1787x; 1.1787x over previous
#include <cuda_runtime.h>
#include <cuda_fp16.h>
#include <math.h>
#include <stdint.h>

#define SS 512
#define BB 256
#define DD 256
#define NROWS (SS*BB)          // 131072
#define JROWS ((SS-2)*BB)      // 130560

// ---------------- scratch ----------------
__device__ __align__(256) __half g_src[(size_t)NROWS*DD];
__device__ __align__(256) __half g_h[(size_t)NROWS*DD];
__device__ __align__(256) __half g_t[(size_t)NROWS*DD];
__device__ __align__(256) __half g_mw[DD*DD];
__device__ __align__(256) __half g_w[DD*2*DD];

// ---------------- helpers ----------------
__device__ __forceinline__ uint32_t smem_u32(const void* p) {
    uint32_t r;
    asm("{ .reg .u64 t; cvta.to.shared.u64 t, %1; cvt.u32.u64 %0, t; }" : "=r"(r) : "l"(p));
    return r;
}
__device__ __forceinline__ void cp16z(uint32_t dst, const void* src, uint32_t sz) {
    asm volatile("cp.async.cg.shared.global [%0], [%1], 16, %2;" :: "r"(dst), "l"(src), "r"(sz));
}
__device__ __forceinline__ void cp16(uint32_t dst, const void* src) {
    asm volatile("cp.async.cg.shared.global [%0], [%1], 16;" :: "r"(dst), "l"(src));
}
__device__ __forceinline__ void ldmx4(uint32_t* r, uint32_t addr) {
    asm volatile("ldmatrix.sync.aligned.m8n8.x4.shared.b16 {%0,%1,%2,%3}, [%4];"
                 : "=r"(r[0]), "=r"(r[1]), "=r"(r[2]), "=r"(r[3]) : "r"(addr));
}
__device__ __forceinline__ void mma16816(float* d, const uint32_t* a, uint32_t b0, uint32_t b1) {
    asm volatile("mma.sync.aligned.m16n8k16.row.col.f32.f16.f16.f32 "
                 "{%0,%1,%2,%3}, {%4,%5,%6,%7}, {%8,%9}, {%0,%1,%2,%3};"
                 : "+f"(d[0]), "+f"(d[1]), "+f"(d[2]), "+f"(d[3])
                 : "r"(a[0]), "r"(a[1]), "r"(a[2]), "r"(a[3]), "r"(b0), "r"(b1));
}
__device__ __forceinline__ float gelu_f(float x) {
    return 0.5f * x * (1.0f + erff(x * 0.7071067811865476f));
}
// swizzled offset within a 128-row x 64-col fp16 tile (128B rows, 8 x 16B chunks)
__device__ __forceinline__ uint32_t swz(int r, int c) {
    return (uint32_t)(r * 128 + ((c ^ (r & 7)) * 16));
}

// ---------------- fp32 -> fp16 ----------------
__global__ void conv_k(const float* __restrict__ in, __half* __restrict__ o, int n) {
    int i = (blockIdx.x * blockDim.x + threadIdx.x) * 4;
    if (i >= n) return;
    float4 v = *(const float4*)(in + i);
    __half2 t;
    t.x = __float2half(v.x); t.y = __float2half(v.y); *(__half2*)(o + i)     = t;
    t.x = __float2half(v.z); t.y = __float2half(v.w); *(__half2*)(o + i + 2) = t;
}

// ---------------- mma.sync GEMM, single fp16 ----------------
// CTA tile 128(M) x 128(N); 8 warps 4(M) x 2(N); warp tile 32x64; K-chunk 64.
// 3-stage cp.async pipeline, fully unrolled chunk loop, hoisted ldmatrix offsets.
#define NSTG 3
#define STGB 32768            // A 16K + W 16K per stage
#define SMEM_BYTES (1024 + NSTG*STGB)

template<int KTOT, int MODE>
__global__ void __launch_bounds__(256, 2) mma_gemm(
    const __half* __restrict__ a1, int a1_off,
    const __half* __restrict__ a2, int a2_off,
    const __half* __restrict__ w,
    const float* __restrict__ bias,
    float* __restrict__ outf, int out_off,
    __half* __restrict__ outh)
{
    constexpr int NCH = KTOT / 64;
    extern __shared__ char smraw[];
    const uint32_t TIL = (smem_u32(smraw) + 1023u) & ~1023u;

    const int tid  = threadIdx.x;
    const int wid  = tid >> 5;
    const int lane = tid & 31;
    const int wm   = wid & 3;
    const int wn   = wid >> 2;
    const int mbase = blockIdx.x * 128;
    const int nbase = blockIdx.y * 128;

    // ---- hoisted per-warp ldmatrix offsets (chunk-invariant) ----
    uint32_t aoffs[4][2], woffs[4][4];
    #pragma unroll
    for (int kh = 0; kh < 4; kh++) {
        const int c0 = kh * 2;
        #pragma unroll
        for (int mf = 0; mf < 2; mf++) {
            int r  = wm * 32 + mf * 16 + (lane & 15);
            int cc = c0 + (lane >> 4);
            aoffs[kh][mf] = swz(r, cc);
        }
        #pragma unroll
        for (int nb = 0; nb < 4; nb++) {
            int r  = wn * 64 + nb * 16 + (lane & 7) + ((lane >> 4) << 3);
            int cc = c0 + ((lane >> 3) & 1);
            woffs[kh][nb] = 16384u + swz(r, cc);
        }
    }

    float acc[2][8][4];
    #pragma unroll
    for (int i = 0; i < 2; i++)
        #pragma unroll
        for (int j = 0; j < 8; j++)
            #pragma unroll
            for (int k = 0; k < 4; k++) acc[i][j][k] = 0.f;

    // ---- loader: v = tid..tid+1536, A half + W half ----
    const int lr  = tid >> 3;          // 0..31  (row group for A), reused for W
    const int lc  = tid & 7;           // 16B chunk index
    auto load_chunk = [&](int c, int stg) {
        const int k = c * 64;
        const __half* A_;
        int aoff, kk;
        if (KTOT == 512 && k >= 256) { A_ = a2; aoff = a2_off; kk = k - 256; }
        else                         { A_ = a1; aoff = a1_off; kk = k; }
        const uint32_t sb = TIL + (uint32_t)stg * STGB;
        // A: 128 rows x 8 chunks; 256 threads -> 4 rows-groups of 32
        #pragma unroll
        for (int rep = 0; rep < 4; rep++) {
            int r = lr + rep * 32;
            int grow = mbase + r + aoff;
            uint32_t sz = 16; int g = grow;
            if (g < 0) { g = 0; sz = 0; }
            cp16z(sb + swz(r, lc), A_ + (size_t)g * DD + kk + lc * 8, sz);
        }
        // W: 128 rows x 8 chunks
        #pragma unroll
        for (int rep = 0; rep < 4; rep++) {
            int r = lr + rep * 32;
            cp16(sb + 16384u + swz(r, lc), w + (size_t)(nbase + r) * KTOT + k + lc * 8);
        }
        asm volatile("cp.async.commit_group;" ::: "memory");
    };

    load_chunk(0, 0);
    if (NCH > 1) load_chunk(1, 1);

    #pragma unroll
    for (int c = 0; c < NCH; ++c) {
        if (c == NCH - 1) asm volatile("cp.async.wait_group 0;" ::: "memory");
        else              asm volatile("cp.async.wait_group 1;" ::: "memory");
        __syncthreads();
        if (c + 2 < NCH) load_chunk(c + 2, (c + 2) % NSTG);

        const uint32_t sA = TIL + (uint32_t)(c % NSTG) * STGB;
        #pragma unroll
        for (int kh = 0; kh < 4; kh++) {
            uint32_t a[2][4];
            #pragma unroll
            for (int mf = 0; mf < 2; mf++)
                ldmx4(a[mf], sA + aoffs[kh][mf]);
            uint32_t b[8][2];
            #pragma unroll
            for (int nb = 0; nb < 4; nb++) {
                uint32_t t4[4];
                ldmx4(t4, sA + woffs[kh][nb]);
                b[2 * nb][0] = t4[0];     b[2 * nb][1] = t4[1];
                b[2 * nb + 1][0] = t4[2]; b[2 * nb + 1][1] = t4[3];
            }
            #pragma unroll
            for (int mf = 0; mf < 2; mf++)
                #pragma unroll
                for (int nf = 0; nf < 8; nf++)
                    mma16816(acc[mf][nf], a[mf], b[nf][0], b[nf][1]);
        }
    }

    // ---------------- epilogue ----------------
    float2 bn[8];
    #pragma unroll
    for (int nf = 0; nf < 8; nf++) {
        int col = nbase + wn * 64 + nf * 8 + (lane & 3) * 2;
        bn[nf].x = bias[col];
        bn[nf].y = bias[col + 1];
    }

    #pragma unroll
    for (int mf = 0; mf < 2; mf++) {
        #pragma unroll
        for (int half = 0; half < 2; half++) {
            const int row = mbase + wm * 32 + mf * 16 + (lane >> 2) + half * 8;
            const int colb = nbase + wn * 64 + (lane & 3) * 2;
            #pragma unroll
            for (int nf = 0; nf < 8; nf++) {
                const int col = colb + nf * 8;
                float g0 = gelu_f(acc[mf][nf][half * 2 + 0] + bn[nf].x);
                float g1 = gelu_f(acc[mf][nf][half * 2 + 1] + bn[nf].y);
                if (MODE == 0) {
                    const size_t ob = (size_t)row * DD + col;
                    __half2 hv;
                    hv.x = __float2half(g0);
                    hv.y = __float2half(g1);
                    *reinterpret_cast<__half2*>(outh + ob) = hv;
                } else if (MODE == 1) {
                    const size_t ob = (size_t)row * DD + col;
                    const int xr = row + a1_off;
                    float2 o;
                    if (xr >= 0) {
                        const size_t xb = (size_t)xr * DD + col;
                        __half2 xh2 = *reinterpret_cast<const __half2*>(a1 + xb);
                        o.x = g0 + __half2float(xh2.x);
                        o.y = g1 + __half2float(xh2.y);
                    } else { o.x = g0; o.y = g1; }
                    *reinterpret_cast<float2*>(outf + ob) = o;
                } else {
                    const size_t ob = (size_t)(row + out_off) * DD + col;
                    float2 o = *reinterpret_cast<float2*>(outf + ob);
                    o.x += g0; o.y += g1;
                    *reinterpret_cast<float2*>(outf + ob) = o;
                }
            }
        }
    }
}

// ---------------- cumsum over axis 0, in place ----------------
__global__ void cumsum_k(float* __restrict__ out) {
    int c = blockIdx.x * blockDim.x + threadIdx.x;
    float run = 0.f;
    #pragma unroll 8
    for (int s = 0; s < SS; s++) {
        size_t idx = (size_t)s * (BB * DD) + c;
        run += out[idx];
        out[idx] = run;
    }
}

extern "C" void kernel_launch(void* const* d_in, const int* in_sizes, int n_in,
                              void* d_out, int out_size)
{
    const float* src = nullptr; const float* map_w = nullptr; const float* bl_w = nullptr;
    const float* map_b = nullptr; const float* bl_b = nullptr;
    for (int i = 0; i < n_in; i++) {
        if (in_sizes[i] == NROWS * DD)       src   = (const float*)d_in[i];
        else if (in_sizes[i] == DD * DD)     map_w = (const float*)d_in[i];
        else if (in_sizes[i] == DD * 2 * DD) bl_w  = (const float*)d_in[i];
        else if (in_sizes[i] == DD) { if (!map_b) map_b = (const float*)d_in[i]; else bl_b = (const float*)d_in[i]; }
    }
    float* out = (float*)d_out;

    __half *sf, *h, *t, *mw, *w;
    cudaGetSymbolAddress((void**)&sf, g_src);
    cudaGetSymbolAddress((void**)&h,  g_h);
    cudaGetSymbolAddress((void**)&t,  g_t);
    cudaGetSymbolAddress((void**)&mw, g_mw);
    cudaGetSymbolAddress((void**)&w,  g_w);

    cudaFuncSetAttribute(mma_gemm<256, 0>, cudaFuncAttributeMaxDynamicSharedMemorySize, SMEM_BYTES);
    cudaFuncSetAttribute(mma_gemm<512, 0>, cudaFuncAttributeMaxDynamicSharedMemorySize, SMEM_BYTES);
    cudaFuncSetAttribute(mma_gemm<512, 1>, cudaFuncAttributeMaxDynamicSharedMemorySize, SMEM_BYTES);
    cudaFuncSetAttribute(mma_gemm<512, 2>, cudaFuncAttributeMaxDynamicSharedMemorySize, SMEM_BYTES);

    conv_k<<<(NROWS * DD / 4 + 255) / 256, 256>>>(src, sf, NROWS * DD);
    conv_k<<<(DD * DD / 4 + 255) / 256, 256>>>(map_w, mw, DD * DD);
    conv_k<<<(DD * 2 * DD / 4 + 255) / 256, 256>>>(bl_w, w, DD * 2 * DD);

    dim3 blk(256);
    dim3 gAll(NROWS / 128, 2);   // 1024 x 2
    dim3 gJ(JROWS / 128, 2);     // 1020 x 2

    // 1) h = gelu(src @ map_w^T + map_b) -> fp16
    mma_gemm<256, 0><<<gAll, blk, SMEM_BYTES>>>(sf, 0, sf, 0, mw, map_b,
                                                nullptr, 0, h);
    // 2) delta = x + blacket(x, h), x = h shifted by one step (BB rows)
    mma_gemm<512, 1><<<gAll, blk, SMEM_BYTES>>>(h, -BB, h, 0, w, bl_b,
                                                out, 0, nullptr);
    // 3) J terms: t = blacket(u, v); out[2B:] += blacket(w, t)
    mma_gemm<512, 0><<<gJ, blk, SMEM_BYTES>>>(h, BB,     h, 2 * BB, w, bl_b,
                                              nullptr, 0, t);
    mma_gemm<512, 2><<<gJ, blk, SMEM_BYTES>>>(h, 0,      t, 0,      w, bl_b,
                                              out, 2 * BB, nullptr);
    mma_gemm<512, 0><<<gJ, blk, SMEM_BYTES>>>(h, 2 * BB, h, 0,      w, bl_b,
                                              nullptr, 0, t);
    mma_gemm<512, 2><<<gJ, blk, SMEM_BYTES>>>(h, BB,     t, 0,      w, bl_b,
                                              out, 2 * BB, nullptr);
    mma_gemm<512, 0><<<gJ, blk, SMEM_BYTES>>>(h, 0,      h, BB,     w, bl_b,
                                              nullptr, 0, t);
    mma_gemm<512, 2><<<gJ, blk, SMEM_BYTES>>>(h, 2 * BB, t, 0,      w, bl_b,
                                              out, 2 * BB, nullptr);
    // 4) cumsum along axis 0
    cumsum_k<<<(BB * DD) / 256, 256>>>(out);
}